// round 8
// baseline (speedup 1.0000x reference)
#include <cuda_runtime.h>

#define N_NODES 50000
#define F       128
#define E_MAX   800000
#define NPB     32      // nodes per block in GEMM
#define KT      32      // weight k-tile
#define KP      (KT + 2) // padded row stride: 136B rows -> conflict-free LDS.64

// ---- static device scratch (no allocs allowed) ----
__device__ int   g_deg[N_NODES];
__device__ int   g_off[N_NODES + 1];
__device__ int   g_cursor[N_NODES];
__device__ int   g_src_sorted[E_MAX];
__device__ float g_agg[N_NODES * F];

// ---- packed fp32x2 helpers (sm_100+; ptxas never auto-emits FFMA2) ----
#define FMA2(d, a, b) asm("fma.rn.f32x2 %0, %1, %2, %0;" : "+l"(d) : "l"(a), "l"(b))
#define UNPACK2(lo, hi, v) asm("mov.b64 {%0, %1}, %2;" : "=f"(lo), "=f"(hi) : "l"(v))

// ---------------------------------------------------------------------------
// CSR build: zero degrees -> histogram -> prefix scan -> reorder src by dst
// ---------------------------------------------------------------------------
__global__ void zero_deg_kernel() {
    int i = blockIdx.x * blockDim.x + threadIdx.x;
    if (i < N_NODES) g_deg[i] = 0;
}

__global__ void hist_kernel(const int* __restrict__ dst, int E) {
    int e = blockIdx.x * blockDim.x + threadIdx.x;
    if (e < E) atomicAdd(&g_deg[dst[e]], 1);
}

__global__ void __launch_bounds__(1024) scan_kernel() {
    __shared__ int wsum[32];
    __shared__ int carry;
    const int t = threadIdx.x, lane = t & 31, wid = t >> 5;
    if (t == 0) carry = 0;
    __syncthreads();
    for (int base = 0; base < N_NODES; base += 1024) {
        int i = base + t;
        int v = (i < N_NODES) ? g_deg[i] : 0;
        int inc = v;
#pragma unroll
        for (int d = 1; d < 32; d <<= 1) {
            int n = __shfl_up_sync(0xffffffffu, inc, d);
            if (lane >= d) inc += n;
        }
        if (lane == 31) wsum[wid] = inc;
        __syncthreads();
        if (wid == 0) {
            int ws = wsum[lane];
            int wi = ws;
#pragma unroll
            for (int d = 1; d < 32; d <<= 1) {
                int n = __shfl_up_sync(0xffffffffu, wi, d);
                if (lane >= d) wi += n;
            }
            wsum[lane] = wi - ws;
        }
        __syncthreads();
        int excl = carry + wsum[wid] + (inc - v);
        if (i < N_NODES) { g_off[i] = excl; g_cursor[i] = excl; }
        __syncthreads();
        if (t == 1023) carry = excl + v;
        __syncthreads();
    }
    if (t == 0) g_off[N_NODES] = carry;
}

__global__ void reorder_kernel(const int* __restrict__ src,
                               const int* __restrict__ dst, int E) {
    int e = blockIdx.x * blockDim.x + threadIdx.x;
    if (e < E) {
        int d = dst[e];
        int pos = atomicAdd(&g_cursor[d], 1);
        g_src_sorted[pos] = src[e];
    }
}

// ---------------------------------------------------------------------------
// Aggregate: one warp per node, neighbor loop unrolled x8 for MLP.
// ---------------------------------------------------------------------------
__global__ void __launch_bounds__(256)
agg_kernel(const float4* __restrict__ x4) {
    int node = (blockIdx.x * blockDim.x + threadIdx.x) >> 5;
    int lane = threadIdx.x & 31;
    if (node >= N_NODES) return;

    int beg = g_off[node];
    int end = g_off[node + 1];
    float4 acc = make_float4(0.f, 0.f, 0.f, 0.f);

    int i = beg;
    for (; i + 8 <= end; i += 8) {
        int s[8];
#pragma unroll
        for (int u = 0; u < 8; u++) s[u] = g_src_sorted[i + u];
        float4 v[8];
#pragma unroll
        for (int u = 0; u < 8; u++) v[u] = x4[s[u] * 32 + lane];
#pragma unroll
        for (int u = 0; u < 8; u++) {
            acc.x += v[u].x; acc.y += v[u].y;
            acc.z += v[u].z; acc.w += v[u].w;
        }
    }
    for (; i < end; i++) {
        int s = g_src_sorted[i];
        float4 v = x4[s * 32 + lane];
        acc.x += v.x; acc.y += v.y; acc.z += v.z; acc.w += v.w;
    }
    reinterpret_cast<float4*>(g_agg)[node * 32 + lane] = acc;
}

// ---------------------------------------------------------------------------
// Dual GEMM + bias + ReLU, k-pair FFMA2 (lo = even-k partial, hi = odd-k).
// 256 threads, 32 nodes/block, 3 blocks/SM. Thread tile: 4 nodes x 4 outputs.
// All smem k-major; 136B row stride => LDS.64 reads conflict-free; staging
// uses float2 stores (8B-aligned; float4 stores would trap on odd rows).
// ---------------------------------------------------------------------------
__global__ void __launch_bounds__(256, 3)
gemm_relu_kernel(const float* __restrict__ x,
                 const float* __restrict__ Wrel,
                 const float* __restrict__ brel,
                 const float* __restrict__ Wroot,
                 float* __restrict__ out) {
    __shared__ __align__(16) float sWrel [128][KP];   // 17.4KB
    __shared__ __align__(16) float sWroot[128][KP];   // 17.4KB
    __shared__ __align__(16) float sA[NPB][KP];       //  4.4KB
    __shared__ __align__(16) float sX[NPB][KP];       //  4.4KB

    const int t  = threadIdx.x;
    const int og = t >> 3;     // 0..31 -> output cols og*4..og*4+3
    const int ng = t & 7;      // nodes ng, ng+8, ng+16, ng+24
    const int nodeBase = blockIdx.x * NPB;

    unsigned long long acc[4][4];   // [node][out] = (even-k, odd-k) partials
#pragma unroll
    for (int n = 0; n < 4; n++)
#pragma unroll
        for (int o = 0; o < 4; o++) acc[n][o] = 0ull;

    for (int kc = 0; kc < F; kc += KT) {
        __syncthreads();

        // --- stage weights k-major: sW[o][kk] = W[o][kc+kk] (float2 stores)
        {
            int o  = t >> 1;            // 0..127
            int kq = (t & 1) * 16;      // 0 or 16
#pragma unroll
            for (int j = 0; j < 4; j++) {
                float4 wr = *reinterpret_cast<const float4*>(&Wrel [o * F + kc + kq + 4 * j]);
                float4 wo = *reinterpret_cast<const float4*>(&Wroot[o * F + kc + kq + 4 * j]);
                *reinterpret_cast<float2*>(&sWrel [o][kq + 4 * j])     = make_float2(wr.x, wr.y);
                *reinterpret_cast<float2*>(&sWrel [o][kq + 4 * j + 2]) = make_float2(wr.z, wr.w);
                *reinterpret_cast<float2*>(&sWroot[o][kq + 4 * j])     = make_float2(wo.x, wo.y);
                *reinterpret_cast<float2*>(&sWroot[o][kq + 4 * j + 2]) = make_float2(wo.z, wo.w);
            }
        }
        // --- stage inputs k-major: 32 nodes x 32 k (float2 stores)
        {
            int slot = t >> 3;          // 0..31
            int kq   = (t & 7) * 4;     // 0,4,...,28
            int node = nodeBase + slot;
            int gc   = node < N_NODES ? node : N_NODES - 1;
            float4 a  = *reinterpret_cast<const float4*>(&g_agg[gc * F + kc + kq]);
            float4 xx = *reinterpret_cast<const float4*>(&x[gc * F + kc + kq]);
            *reinterpret_cast<float2*>(&sA[slot][kq])     = make_float2(a.x, a.y);
            *reinterpret_cast<float2*>(&sA[slot][kq + 2]) = make_float2(a.z, a.w);
            *reinterpret_cast<float2*>(&sX[slot][kq])     = make_float2(xx.x, xx.y);
            *reinterpret_cast<float2*>(&sX[slot][kq + 2]) = make_float2(xx.z, xx.w);
        }
        __syncthreads();

        // --- compute: per kk2 (2 k's): 16 LDS.64 + 32 FFMA2, zero MOVs
#pragma unroll
        for (int kk2 = 0; kk2 < KT / 2; kk2++) {
            const int kb = kk2 * 2;
            unsigned long long wr[4], wo[4];
#pragma unroll
            for (int o = 0; o < 4; o++) {
                wr[o] = *reinterpret_cast<const unsigned long long*>(&sWrel [og * 4 + o][kb]);
                wo[o] = *reinterpret_cast<const unsigned long long*>(&sWroot[og * 4 + o][kb]);
            }
#pragma unroll
            for (int n = 0; n < 4; n++) {
                unsigned long long a2 = *reinterpret_cast<const unsigned long long*>(&sA[ng + 8 * n][kb]);
                unsigned long long x2 = *reinterpret_cast<const unsigned long long*>(&sX[ng + 8 * n][kb]);
#pragma unroll
                for (int o = 0; o < 4; o++) {
                    FMA2(acc[n][o], a2, wr[o]);
                    FMA2(acc[n][o], x2, wo[o]);
                }
            }
        }
    }

    // ---- epilogue: fold k-pair partials, bias + relu + store ----
    float4 b4 = *reinterpret_cast<const float4*>(&brel[og * 4]);
    const float* bp = reinterpret_cast<const float*>(&b4);
#pragma unroll
    for (int n = 0; n < 4; n++) {
        int node = nodeBase + ng + 8 * n;
        if (node < N_NODES) {
            float4 r;
            float* rp = reinterpret_cast<float*>(&r);
#pragma unroll
            for (int o = 0; o < 4; o++) {
                float lo, hi;
                UNPACK2(lo, hi, acc[n][o]);
                rp[o] = fmaxf((lo + hi) + bp[o], 0.f);
            }
            *reinterpret_cast<float4*>(&out[node * F + og * 4]) = r;
        }
    }
}

// ---------------------------------------------------------------------------
extern "C" void kernel_launch(void* const* d_in, const int* in_sizes, int n_in,
                              void* d_out, int out_size) {
    const float* x     = (const float*)d_in[0];
    const int*   ei    = (const int*)d_in[1];     // int32 (JAX x64 disabled)
    const float* Wrel  = (const float*)d_in[2];
    const float* brel  = (const float*)d_in[3];
    const float* Wroot = (const float*)d_in[4];
    float*       out   = (float*)d_out;

    const int E = in_sizes[1] / 2;                // 800000
    const int* src = ei;
    const int* dst = ei + E;

    // 1) CSR build
    zero_deg_kernel<<<(N_NODES + 255) / 256, 256>>>();
    hist_kernel<<<(E + 255) / 256, 256>>>(dst, E);
    scan_kernel<<<1, 1024>>>();
    reorder_kernel<<<(E + 255) / 256, 256>>>(src, dst, E);

    // 2) aggregate: warp per node
    agg_kernel<<<(N_NODES * 32 + 255) / 256, 256>>>(
        reinterpret_cast<const float4*>(x));

    // 3) dual GEMM + bias + relu (static smem 42.5KB, 3 blocks/SM)
    gemm_relu_kernel<<<(N_NODES + NPB - 1) / NPB, 256>>>(
        x, Wrel, brel, Wroot, out);
}